// round 10
// baseline (speedup 1.0000x reference)
#include <cuda_runtime.h>
#include <math.h>

// Shape (fixed): B=16, L=512, H=8, D=64, k = int(log 512) = 6
// Identity: sum_t irfft(conj(Q)*K)[t] = (sum_d q)(sum_d k), so
// x_corr_mean[b,l] = (1/(H*L)) * sum_h (sum_d q[b,l,h,:]) (sum_d k[b,l,h,:]).

#define B_ 16
#define L_ 512
#define H_ 8
#define HD_ 512
#define K_TOP 6

__device__ float g_scores[B_ * L_];

// ---------------------------------------------------------------------------
// Kernel 1 (round-3 proven): score[b,l] = (1/4096) * sum_h (sum_d q)(sum_d k)
// One block per (b,l) row, 128 threads, float4 loads. HBM-bound (33.5 MB).
// ---------------------------------------------------------------------------
__global__ __launch_bounds__(128) void score_kernel(
    const float* __restrict__ q, const float* __restrict__ k)
{
    const int bl = blockIdx.x;
    const int t  = threadIdx.x;
    const float4* qp = reinterpret_cast<const float4*>(q + (size_t)bl * HD_);
    const float4* kp = reinterpret_cast<const float4*>(k + (size_t)bl * HD_);

    float4 q4 = qp[t];
    float4 k4 = kp[t];
    float qs = q4.x + q4.y + q4.z + q4.w;
    float ks = k4.x + k4.y + k4.z + k4.w;

    // Segmented 16-lane reduction (one head per 16-lane group).
    #pragma unroll
    for (int o = 8; o > 0; o >>= 1) {
        qs += __shfl_down_sync(0xFFFFFFFFu, qs, o);
        ks += __shfl_down_sync(0xFFFFFFFFu, ks, o);
    }

    __shared__ float sq[H_], sk[H_];
    if ((t & 15) == 0) {
        sq[t >> 4] = qs;
        sk[t >> 4] = ks;
    }
    __syncthreads();

    if (t == 0) {
        float tot = 0.0f;
        #pragma unroll
        for (int h = 0; h < H_; h++)
            tot += sq[h] * sk[h];
        g_scores[bl] = tot * (1.0f / (H_ * L_));
        // PDL: let the dependent kernel begin launching while stores drain.
        cudaTriggerProgrammaticLaunchCompletion();
    }
}

// ---------------------------------------------------------------------------
// Kernel 2: per-batch top-6 + softmax + gather. 16 blocks x 128 threads.
// ZERO barriers / smem: all 4 warps redundantly compute the identical top-6
// and softmax in registers (u64 packed argmax), then every thread gathers.
// ---------------------------------------------------------------------------
__device__ __forceinline__ unsigned long long packKI(float v, int idx) {
    unsigned int b = __float_as_uint(v);
    b = (b & 0x80000000u) ? ~b : (b | 0x80000000u);   // order-preserving
    return ((unsigned long long)b << 32) | (unsigned int)(L_ - 1 - idx);
}
__device__ __forceinline__ float unpackV(unsigned long long p) {
    unsigned int u = (unsigned int)(p >> 32);
    u = (u & 0x80000000u) ? (u ^ 0x80000000u) : ~u;
    return __uint_as_float(u);
}
__device__ __forceinline__ int unpackI(unsigned long long p) {
    return L_ - 1 - (int)(p & 0xFFFFFFFFu);
}
__device__ __forceinline__ unsigned long long u64max(unsigned long long a,
                                                    unsigned long long b) {
    return a > b ? a : b;
}

__global__ __launch_bounds__(128) void topk_agg_kernel(
    const float* __restrict__ values, float* __restrict__ out)
{
    // Wait for score_kernel's grid to fully complete (memory visible).
    cudaGridDependencySynchronize();

    const int b    = blockIdx.x;        // 0..15
    const int t    = threadIdx.x;       // 0..127
    const int lane = t & 31;

    // Each lane owns 16 scores (4 x float4), packed as order-preserving u64.
    const float4* sp = reinterpret_cast<const float4*>(g_scores + b * L_);
    unsigned long long pk[16];
    #pragma unroll
    for (int v4i = 0; v4i < 4; v4i++) {
        float4 s4 = sp[lane * 4 + v4i];
        int base = lane * 16 + v4i * 4;
        pk[v4i * 4 + 0] = packKI(s4.x, base + 0);
        pk[v4i * 4 + 1] = packKI(s4.y, base + 1);
        pk[v4i * 4 + 2] = packKI(s4.z, base + 2);
        pk[v4i * 4 + 3] = packKI(s4.w, base + 3);
    }

    unsigned long long top[K_TOP];
    #pragma unroll
    for (int r = 0; r < K_TOP; r++) {
        // Local tree max over 16 (integer max ops, depth 4).
        unsigned long long m01 = u64max(u64max(pk[0],  pk[1]),  u64max(pk[2],  pk[3]));
        unsigned long long m23 = u64max(u64max(pk[4],  pk[5]),  u64max(pk[6],  pk[7]));
        unsigned long long m45 = u64max(u64max(pk[8],  pk[9]),  u64max(pk[10], pk[11]));
        unsigned long long m67 = u64max(u64max(pk[12], pk[13]), u64max(pk[14], pk[15]));
        unsigned long long m = u64max(u64max(m01, m23), u64max(m45, m67));
        // Warp max (5 shuffle steps).
        #pragma unroll
        for (int o = 16; o > 0; o >>= 1)
            m = u64max(m, __shfl_xor_sync(0xFFFFFFFFu, m, o));
        top[r] = m;
        int idx = unpackI(m);
        if ((idx >> 4) == lane) pk[idx & 15] = 0ull;   // knockout in owner lane
    }

    // Softmax over the 6 logits (top[0] is the max) — redundant per thread.
    float m0 = unpackV(top[0]);
    float w[K_TOP];
    float s = 0.0f;
    #pragma unroll
    for (int i = 0; i < K_TOP; i++) { w[i] = __expf(unpackV(top[i]) - m0); s += w[i]; }
    float inv = 1.0f / s;

    // out[b, t*4 .. t*4+3] = sum_i w[i] * V[b, idx_i, t*4 .. ]
    const float4* vb = reinterpret_cast<const float4*>(values) + (size_t)b * L_ * 128;
    float4 acc = make_float4(0.f, 0.f, 0.f, 0.f);
    #pragma unroll
    for (int i = 0; i < K_TOP; i++) {
        float wi = w[i] * inv;
        float4 v4 = vb[(size_t)unpackI(top[i]) * 128 + t];
        acc.x = fmaf(wi, v4.x, acc.x);
        acc.y = fmaf(wi, v4.y, acc.y);
        acc.z = fmaf(wi, v4.z, acc.z);
        acc.w = fmaf(wi, v4.w, acc.w);
    }
    reinterpret_cast<float4*>(out)[(size_t)b * 128 + t] = acc;
}

extern "C" void kernel_launch(void* const* d_in, const int* in_sizes, int n_in,
                              void* d_out, int out_size)
{
    const float* q = (const float*)d_in[0];
    const float* k = (const float*)d_in[1];
    const float* v = (const float*)d_in[2];
    float* out = (float*)d_out;

    score_kernel<<<B_ * L_, 128>>>(q, k);

    // PDL launch: kernel 2 may begin (prologue) while kernel 1 drains;
    // cudaGridDependencySynchronize() inside gates the actual reads.
    cudaLaunchConfig_t cfg = {};
    cfg.gridDim  = dim3(B_);
    cfg.blockDim = dim3(128);
    cfg.dynamicSmemBytes = 0;
    cfg.stream = 0;
    cudaLaunchAttribute attr[1];
    attr[0].id = cudaLaunchAttributeProgrammaticStreamSerialization;
    attr[0].val.programmaticStreamSerializationAllowed = 1;
    cfg.attrs = attr;
    cfg.numAttrs = 1;
    cudaLaunchKernelEx(&cfg, topk_agg_kernel, v, out);
}

// round 11
// speedup vs baseline: 1.0152x; 1.0152x over previous
#include <cuda_runtime.h>
#include <math.h>

// Shape (fixed): B=16, L=512, H=8, D=64, k = int(log 512) = 6
// Identity: sum_t irfft(conj(Q)*K)[t] = (sum_d q)(sum_d k), so
// x_corr_mean[b,l] = (1/(H*L)) * sum_h (sum_d q[b,l,h,:]) (sum_d k[b,l,h,:]).
//
// Single fused kernel. Phase 1 is byte-for-byte the proven round-3 score
// kernel (one 128-thread block per row). Phase 2 (top-6 + softmax + gather)
// runs ONLY in warp 0 of the last-arriving block of each batch, selected by
// one acq_rel atomic (release orders the score store; no fences, no extra
// barriers). Counters are monotonic (512 | 2^32) -> graph-replay safe.

#define B_ 16
#define L_ 512
#define H_ 8
#define HD_ 512
#define K_TOP 6

__device__ float g_scores[B_ * L_];
__device__ unsigned int g_cnt[B_];   // never reset; +512 per batch per launch

// Order-preserving (score,index) pack: bigger score wins, ties -> lower index.
__device__ __forceinline__ unsigned long long packKI(float v, int idx) {
    unsigned int b = __float_as_uint(v);
    b = (b & 0x80000000u) ? ~b : (b | 0x80000000u);
    return ((unsigned long long)b << 32) | (unsigned int)(L_ - 1 - idx);
}
__device__ __forceinline__ float unpackV(unsigned long long p) {
    unsigned int u = (unsigned int)(p >> 32);
    u = (u & 0x80000000u) ? (u ^ 0x80000000u) : ~u;
    return __uint_as_float(u);
}
__device__ __forceinline__ int unpackI(unsigned long long p) {
    return L_ - 1 - (int)(p & 0xFFFFFFFFu);
}
__device__ __forceinline__ unsigned long long u64max(unsigned long long a,
                                                    unsigned long long b) {
    return a > b ? a : b;
}

__global__ __launch_bounds__(128, 12) void fused_kernel(
    const float* __restrict__ q, const float* __restrict__ k,
    const float* __restrict__ values, float* __restrict__ out)
{
    const int bl = blockIdx.x;          // row 0..8191
    const int b  = bl >> 9;             // batch
    const int t  = threadIdx.x;         // 0..127

    // ---- Phase 1 (identical to the proven score kernel) ------------------
    const float4* qp = reinterpret_cast<const float4*>(q + (size_t)bl * HD_);
    const float4* kp = reinterpret_cast<const float4*>(k + (size_t)bl * HD_);

    float4 q4 = qp[t];
    float4 k4 = kp[t];
    float qs = q4.x + q4.y + q4.z + q4.w;
    float ks = k4.x + k4.y + k4.z + k4.w;

    #pragma unroll
    for (int o = 8; o > 0; o >>= 1) {
        qs += __shfl_down_sync(0xFFFFFFFFu, qs, o);
        ks += __shfl_down_sync(0xFFFFFFFFu, ks, o);
    }

    __shared__ float sq[H_], sk[H_];
    if ((t & 15) == 0) {
        sq[t >> 4] = qs;
        sk[t >> 4] = ks;
    }
    __syncthreads();

    // Warps 1..3 are done (no barriers past this point).
    if (t >= 32) return;

    int win = 0;
    if (t == 0) {
        float tot = 0.0f;
        #pragma unroll
        for (int h = 0; h < H_; h++) tot += sq[h] * sk[h];
        g_scores[bl] = tot * (1.0f / (H_ * L_));
        unsigned int old;
        // release: orders the score store above; acquire: orders winner reads.
        asm volatile("atom.acq_rel.gpu.global.add.u32 %0, [%1], %2;"
                     : "=r"(old) : "l"(g_cnt + b), "r"(1u) : "memory");
        win = ((old & (unsigned)(L_ - 1)) == (unsigned)(L_ - 1));
    }
    win = __shfl_sync(0xFFFFFFFFu, win, 0);
    if (!win) return;

    // ---- Phase 2 (winner block's warp 0 only) ----------------------------
    const int lane = t;

    // 16 scores per lane (4 x float4), L2-direct.
    const float4* sp = reinterpret_cast<const float4*>(g_scores + b * L_);
    unsigned long long pk[16];
    #pragma unroll
    for (int v4i = 0; v4i < 4; v4i++) {
        float4 s4 = __ldcg(sp + lane * 4 + v4i);
        int base = lane * 16 + v4i * 4;
        pk[v4i * 4 + 0] = packKI(s4.x, base + 0);
        pk[v4i * 4 + 1] = packKI(s4.y, base + 1);
        pk[v4i * 4 + 2] = packKI(s4.z, base + 2);
        pk[v4i * 4 + 3] = packKI(s4.w, base + 3);
    }

    unsigned long long top[K_TOP];
    #pragma unroll
    for (int r = 0; r < K_TOP; r++) {
        unsigned long long m01 = u64max(u64max(pk[0],  pk[1]),  u64max(pk[2],  pk[3]));
        unsigned long long m23 = u64max(u64max(pk[4],  pk[5]),  u64max(pk[6],  pk[7]));
        unsigned long long m45 = u64max(u64max(pk[8],  pk[9]),  u64max(pk[10], pk[11]));
        unsigned long long m67 = u64max(u64max(pk[12], pk[13]), u64max(pk[14], pk[15]));
        unsigned long long m = u64max(u64max(m01, m23), u64max(m45, m67));
        #pragma unroll
        for (int o = 16; o > 0; o >>= 1)
            m = u64max(m, __shfl_xor_sync(0xFFFFFFFFu, m, o));
        top[r] = m;
        int idx = unpackI(m);
        if ((idx >> 4) == lane) pk[idx & 15] = 0ull;   // knockout in owner lane
    }

    // Softmax (top[0] is the max) — redundant in every lane, no broadcast.
    float m0 = unpackV(top[0]);
    float w[K_TOP];
    float s = 0.0f;
    #pragma unroll
    for (int i = 0; i < K_TOP; i++) { w[i] = __expf(unpackV(top[i]) - m0); s += w[i]; }
    float inv = 1.0f / s;

    // out[b,:] = sum_i w[i] * V[b, idx_i, :]  (128 float4, 4 per lane).
    const float4* vb = reinterpret_cast<const float4*>(values) + (size_t)b * L_ * 128;
    float4 acc[4];
    #pragma unroll
    for (int j = 0; j < 4; j++) acc[j] = make_float4(0.f, 0.f, 0.f, 0.f);

    #pragma unroll
    for (int i = 0; i < K_TOP; i++) {
        float wi = w[i] * inv;
        const float4* vp = vb + (size_t)unpackI(top[i]) * 128 + lane;
        #pragma unroll
        for (int j = 0; j < 4; j++) {
            float4 v4 = __ldg(vp + 32 * j);
            acc[j].x = fmaf(wi, v4.x, acc[j].x);
            acc[j].y = fmaf(wi, v4.y, acc[j].y);
            acc[j].z = fmaf(wi, v4.z, acc[j].z);
            acc[j].w = fmaf(wi, v4.w, acc[j].w);
        }
    }
    float4* op = reinterpret_cast<float4*>(out) + (size_t)b * 128 + lane;
    #pragma unroll
    for (int j = 0; j < 4; j++) op[32 * j] = acc[j];
}

extern "C" void kernel_launch(void* const* d_in, const int* in_sizes, int n_in,
                              void* d_out, int out_size)
{
    const float* q = (const float*)d_in[0];
    const float* k = (const float*)d_in[1];
    const float* v = (const float*)d_in[2];
    float* out = (float*)d_out;

    fused_kernel<<<B_ * L_, 128>>>(q, k, v, out);
}

// round 13
// speedup vs baseline: 1.3434x; 1.3233x over previous
#include <cuda_runtime.h>
#include <math.h>

// Shape (fixed): B=16, L=512, H=8, D=64, k = int(log 512) = 6
// Identity: sum_t irfft(conj(Q)*K)[t] = (sum_d q)(sum_d k), so
// x_corr_mean[b,l] = (1/(H*L)) * sum_h (sum_d q[b,l,h,:]) (sum_d k[b,l,h,:]).
//
// Fused kernel, atomic-lean arrival protocol:
//   1024 blocks x 256 threads; warp w computes row blockIdx.x*8+w.
//   ONE acq_rel atomic per BLOCK (64 per batch counter, vs 512 per-row in
//   earlier rounds whose same-address ATOMG chains serialized ~8us).
//   bar.sync orders all warps' score stores before thread 0's release-RMW.
//   The 64th arriver's warp 0 runs top-6 + softmax + gather for its batch.
//   Counters monotonic (64 | 2^32) -> graph-replay safe.

#define B_ 16
#define L_ 512
#define H_ 8
#define HD_ 512
#define K_TOP 6
#define ROWS_PER_BLK 8
#define BLKS_PER_BATCH 64   // 512 / 8

__device__ float g_scores[B_ * L_];
__device__ unsigned int g_cnt[B_];   // never reset; +64 per batch per launch

// Order-preserving (score,index) pack: bigger score wins, ties -> lower index.
__device__ __forceinline__ unsigned long long packKI(float v, int idx) {
    unsigned int b = __float_as_uint(v);
    b = (b & 0x80000000u) ? ~b : (b | 0x80000000u);
    return ((unsigned long long)b << 32) | (unsigned int)(L_ - 1 - idx);
}
__device__ __forceinline__ float unpackV(unsigned long long p) {
    unsigned int u = (unsigned int)(p >> 32);
    u = (u & 0x80000000u) ? (u ^ 0x80000000u) : ~u;
    return __uint_as_float(u);
}
__device__ __forceinline__ int unpackI(unsigned long long p) {
    return L_ - 1 - (int)(p & 0xFFFFFFFFu);
}
__device__ __forceinline__ unsigned long long u64max(unsigned long long a,
                                                    unsigned long long b) {
    return a > b ? a : b;
}

__global__ __launch_bounds__(256, 6) void fused_kernel(
    const float* __restrict__ q, const float* __restrict__ k,
    const float* __restrict__ values, float* __restrict__ out)
{
    const int lane = threadIdx.x & 31;
    const int w    = threadIdx.x >> 5;                 // warp 0..7
    const int bl   = blockIdx.x * ROWS_PER_BLK + w;    // row 0..8191
    const int b    = blockIdx.x >> 6;                  // batch (all 8 rows same)

    // ---- Phase 1: one warp per row (proven round-6 numerics) -------------
    // Row = 128 float4; lane loads float4 lane, lane+32, lane+64, lane+96.
    const float4* qp = reinterpret_cast<const float4*>(q) + (size_t)bl * 128;
    const float4* kp = reinterpret_cast<const float4*>(k) + (size_t)bl * 128;

    float qs[4], ks[4];
    #pragma unroll
    for (int j = 0; j < 4; j++) {
        float4 q4 = __ldg(qp + lane + 32 * j);
        float4 k4 = __ldg(kp + lane + 32 * j);
        qs[j] = q4.x + q4.y + q4.z + q4.w;
        ks[j] = k4.x + k4.y + k4.z + k4.w;
    }
    // Segmented reduce within each 16-lane half (8 head-chains).
    #pragma unroll
    for (int o = 8; o > 0; o >>= 1) {
        #pragma unroll
        for (int j = 0; j < 4; j++) {
            qs[j] += __shfl_down_sync(0xFFFFFFFFu, qs[j], o);
            ks[j] += __shfl_down_sync(0xFFFFFFFFu, ks[j], o);
        }
    }
    // Lane 0 holds heads {0,2,4,6}; lane 16 holds {1,3,5,7}.
    float p = qs[0] * ks[0] + qs[1] * ks[1] + qs[2] * ks[2] + qs[3] * ks[3];
    p += __shfl_down_sync(0xFFFFFFFFu, p, 16);
    if (lane == 0)
        g_scores[bl] = p * (1.0f / (H_ * L_));

    // ---- Arrival: ONE atomic per block ----------------------------------
    __shared__ int s_win;
    __syncthreads();   // orders all 8 score stores before the release-RMW
    if (threadIdx.x == 0) {
        unsigned int old;
        asm volatile("atom.acq_rel.gpu.global.add.u32 %0, [%1], %2;"
                     : "=r"(old) : "l"(g_cnt + b), "r"(1u) : "memory");
        s_win = ((old & (unsigned)(BLKS_PER_BATCH - 1)) ==
                 (unsigned)(BLKS_PER_BATCH - 1));
    }
    __syncthreads();
    if (!s_win || w != 0) return;

    // ---- Phase 2 (winner block's warp 0): top-6 + softmax + gather -------
    const float4* sp = reinterpret_cast<const float4*>(g_scores + b * L_);
    unsigned long long pk[16];
    #pragma unroll
    for (int v4i = 0; v4i < 4; v4i++) {
        float4 s4 = __ldcg(sp + lane * 4 + v4i);
        int base = lane * 16 + v4i * 4;
        pk[v4i * 4 + 0] = packKI(s4.x, base + 0);
        pk[v4i * 4 + 1] = packKI(s4.y, base + 1);
        pk[v4i * 4 + 2] = packKI(s4.z, base + 2);
        pk[v4i * 4 + 3] = packKI(s4.w, base + 3);
    }

    unsigned long long top[K_TOP];
    #pragma unroll
    for (int r = 0; r < K_TOP; r++) {
        unsigned long long m01 = u64max(u64max(pk[0],  pk[1]),  u64max(pk[2],  pk[3]));
        unsigned long long m23 = u64max(u64max(pk[4],  pk[5]),  u64max(pk[6],  pk[7]));
        unsigned long long m45 = u64max(u64max(pk[8],  pk[9]),  u64max(pk[10], pk[11]));
        unsigned long long m67 = u64max(u64max(pk[12], pk[13]), u64max(pk[14], pk[15]));
        unsigned long long m = u64max(u64max(m01, m23), u64max(m45, m67));
        #pragma unroll
        for (int o = 16; o > 0; o >>= 1)
            m = u64max(m, __shfl_xor_sync(0xFFFFFFFFu, m, o));
        top[r] = m;
        int idx = unpackI(m);
        if ((idx >> 4) == lane) pk[idx & 15] = 0ull;   // knockout in owner lane
    }

    // Softmax (top[0] is the max) — redundant per lane, no broadcast needed.
    float m0 = unpackV(top[0]);
    float wgt[K_TOP];
    float s = 0.0f;
    #pragma unroll
    for (int i = 0; i < K_TOP; i++) { wgt[i] = __expf(unpackV(top[i]) - m0); s += wgt[i]; }
    float inv = 1.0f / s;

    // out[b,:] = sum_i w[i] * V[b, idx_i, :]  (128 float4, 4 per lane).
    const float4* vb = reinterpret_cast<const float4*>(values) + (size_t)b * L_ * 128;
    float4 acc[4];
    #pragma unroll
    for (int j = 0; j < 4; j++) acc[j] = make_float4(0.f, 0.f, 0.f, 0.f);

    #pragma unroll
    for (int i = 0; i < K_TOP; i++) {
        float wi = wgt[i] * inv;
        const float4* vp = vb + (size_t)unpackI(top[i]) * 128 + lane;
        #pragma unroll
        for (int j = 0; j < 4; j++) {
            float4 v4 = __ldg(vp + 32 * j);
            acc[j].x = fmaf(wi, v4.x, acc[j].x);
            acc[j].y = fmaf(wi, v4.y, acc[j].y);
            acc[j].z = fmaf(wi, v4.z, acc[j].z);
            acc[j].w = fmaf(wi, v4.w, acc[j].w);
        }
    }
    float4* op = reinterpret_cast<float4*>(out) + (size_t)b * 128 + lane;
    #pragma unroll
    for (int j = 0; j < 4; j++) op[32 * j] = acc[j];
}

extern "C" void kernel_launch(void* const* d_in, const int* in_sizes, int n_in,
                              void* d_out, int out_size)
{
    const float* q = (const float*)d_in[0];
    const float* k = (const float*)d_in[1];
    const float* v = (const float*)d_in[2];
    float* out = (float*)d_out;

    fused_kernel<<<(B_ * L_) / ROWS_PER_BLK, 256>>>(q, k, v, out);
}